// round 16
// baseline (speedup 1.0000x reference)
#include <cuda_runtime.h>
#include <cuda_fp16.h>
#include <cstdint>
#include <cstddef>

#define S_LEN 2048
#define B_DIM 8
#define E_DIM 1024
#define M_TOT (S_LEN*B_DIM)      // 16384
#define CH    (B_DIM*E_DIM)      // 8192
#define NCHUNK 256
#define CLEN  (S_LEN/NCHUNK)     // 8
#define CH8   (CH/8)             // 1024

// ---------------- scratch (device globals; no allocation allowed) ------------
__device__ __half g_xk[(size_t)M_TOT*E_DIM];
__device__ __half g_xv[(size_t)M_TOT*E_DIM];
__device__ __half g_r [(size_t)M_TOT*E_DIM];
__device__ __half g_kh[(size_t)M_TOT*E_DIM];
__device__ __half g_vh[(size_t)M_TOT*E_DIM];
__device__ __half g_wkt[(size_t)E_DIM*E_DIM];
__device__ __half g_wvt[(size_t)E_DIM*E_DIM];
__device__ __half g_wot[(size_t)E_DIM*E_DIM];
__device__ float g_agg[3*(size_t)NCHUNK*CH];
__device__ float g_pre[3*(size_t)NCHUNK*CH];

// ---------------- helpers ----------------------------------------------------
__device__ __forceinline__ uint32_t smem_addr(const void* p) {
    uint32_t a;
    asm("{ .reg .u64 t; cvta.to.shared.u64 t, %1; cvt.u32.u64 %0, t; }" : "=r"(a) : "l"(p));
    return a;
}
#define CP_ASYNC16(dst, src) \
    asm volatile("cp.async.cg.shared.global [%0], [%1], 16;" :: "r"(dst), "l"(src) : "memory")
#define CP_COMMIT() asm volatile("cp.async.commit_group;" ::: "memory")
#define CP_WAIT(n)  asm volatile("cp.async.wait_group %0;" :: "n"(n) : "memory")

#define LDSM4(r, addr) \
    asm volatile("ldmatrix.sync.aligned.m8n8.x4.shared.b16 {%0,%1,%2,%3}, [%4];" \
        : "=r"((r)[0]), "=r"((r)[1]), "=r"((r)[2]), "=r"((r)[3]) : "r"(addr))

__device__ __forceinline__ void mma_f16(float c[4], const uint32_t a[4], const uint32_t b[2]) {
    asm volatile(
        "mma.sync.aligned.m16n8k16.row.col.f32.f16.f16.f32 "
        "{%0,%1,%2,%3}, {%4,%5,%6,%7}, {%8,%9}, {%0,%1,%2,%3};\n"
        : "+f"(c[0]), "+f"(c[1]), "+f"(c[2]), "+f"(c[3])
        : "r"(a[0]), "r"(a[1]), "r"(a[2]), "r"(a[3]), "r"(b[0]), "r"(b[1]));
}

// ============================================================
// 1) fused prep: token mix + fp16 quantize  AND  3x weight transpose
// ============================================================
#define MIXB (M_TOT*E_DIM/4/256)   // 16384

__global__ void prep_kernel(const float* __restrict__ x,
                            const float* __restrict__ tmrkv,
                            const float* __restrict__ Wk,
                            const float* __restrict__ Wv,
                            const float* __restrict__ Wout) {
    __shared__ float t[32][33];
    int blk = blockIdx.x;
    int tid = threadIdx.x;

    if (blk < MIXB) {
        int i4  = blk * 256 + tid;
        int idx = i4 * 4;
        int e   = idx & (E_DIM - 1);
        float4 xc = *(const float4*)(x + idx);
        float4 xp = make_float4(0.f, 0.f, 0.f, 0.f);
        if (idx >= CH) xp = *(const float4*)(x + idx - CH);
        float4 mk = *(const float4*)(tmrkv + E_DIM   + e);
        float4 mv = *(const float4*)(tmrkv + 2*E_DIM + e);
        float ok[4], ov[4];
        ok[0] = mk.x*xc.x + (1.f-mk.x)*xp.x;  ov[0] = mv.x*xc.x + (1.f-mv.x)*xp.x;
        ok[1] = mk.y*xc.y + (1.f-mk.y)*xp.y;  ov[1] = mv.y*xc.y + (1.f-mv.y)*xp.y;
        ok[2] = mk.z*xc.z + (1.f-mk.z)*xp.z;  ov[2] = mv.z*xc.z + (1.f-mv.z)*xp.z;
        ok[3] = mk.w*xc.w + (1.f-mk.w)*xp.w;  ov[3] = mv.w*xc.w + (1.f-mv.w)*xp.w;
        ushort4 kq, vq;
        kq.x = __half_as_ushort(__float2half_rn(ok[0]));
        kq.y = __half_as_ushort(__float2half_rn(ok[1]));
        kq.z = __half_as_ushort(__float2half_rn(ok[2]));
        kq.w = __half_as_ushort(__float2half_rn(ok[3]));
        vq.x = __half_as_ushort(__float2half_rn(ov[0]));
        vq.y = __half_as_ushort(__float2half_rn(ov[1]));
        vq.z = __half_as_ushort(__float2half_rn(ov[2]));
        vq.w = __half_as_ushort(__float2half_rn(ov[3]));
        *(ushort4*)((unsigned short*)g_xk + idx) = kq;
        *(ushort4*)((unsigned short*)g_xv + idx) = vq;
    } else {
        int wb   = blk - MIXB;
        int widx = wb >> 10;          // 0,1,2
        int tb   = wb & 1023;
        const float* W = (widx == 0) ? Wk : (widx == 1) ? Wv : Wout;
        __half* T = (widx == 0) ? g_wkt : (widx == 1) ? g_wvt : g_wot;
        int bx = (tb & 31) * 32;      // n block
        int by = (tb >> 5) * 32;      // k block
        int tx = tid & 31, ty = tid >> 5;   // 32 x 8
        for (int j = ty; j < 32; j += 8)
            t[j][tx] = W[(size_t)(by + j) * E_DIM + bx + tx];
        __syncthreads();
        for (int j = ty; j < 32; j += 8) {
            float v = t[tx][j];
            T[(size_t)(bx + j) * E_DIM + by + tx] = __float2half_rn(v);
        }
    }
}

// ============================================================
// 2) 1-product fp16 GEMM core (128x128 tile, BK=64, 256 thr, NSTG=3)
// ============================================================
#define BM 128
#define BN 128
#define BK 64
#define TILE_B 16384               // 128 rows * 128 bytes
#define STAGE_B (2*TILE_B)         // 32768
#define NSTG 3
#define GEMM_SMEM (NSTG*STAGE_B)   // 98304 -> 2 CTAs/SM

__device__ __forceinline__ void gemm_core(const __half* __restrict__ Aq,
                                          const __half* __restrict__ Bq,
                                          int bm, int bn,
                                          uint32_t sbase, int tid,
                                          float acc[2][8][4]) {
    int warp = tid >> 5, lane = tid & 31;
    int wm = warp & 3, wn = warp >> 2;

    const char* srcs[2] = {
        (const char*)(Aq + (size_t)bm * E_DIM),
        (const char*)(Bq + (size_t)bn * E_DIM) };

    auto load_tile = [&](int kt, int stg) {
        uint32_t dst0 = sbase + (uint32_t)stg * STAGE_B;
        int koff = kt * (BK*2);    // 128 bytes per k-tile
        #pragma unroll
        for (int arr = 0; arr < 2; arr++) {
            #pragma unroll
            for (int i = 0; i < 4; i++) {
                int f = tid + i*256;
                int row = f >> 3, chunk = f & 7;
                int ksl = chunk >> 2, ch = chunk & 3;
                int sw = ch ^ ((row >> 1) & 3);
                uint32_t dst = dst0 + arr*TILE_B + ksl*8192 + row*64 + sw*16;
                const char* src = srcs[arr] + (size_t)row * (E_DIM*2) + koff + chunk*16;
                CP_ASYNC16(dst, src);
            }
        }
    };

    int lm = lane & 7, lg = lane >> 3;
    uint32_t aoff[2];
    #pragma unroll
    for (int mt = 0; mt < 2; mt++) {
        int row = wm*32 + mt*16 + (lg & 1)*8 + lm;
        int swc = (lg >> 1) ^ ((row >> 1) & 3);
        aoff[mt] = (uint32_t)(row*64 + swc*16);
    }
    uint32_t boff[4];
    #pragma unroll
    for (int j = 0; j < 4; j++) {
        int row = wn*64 + j*16 + (lg >> 1)*8 + lm;
        int swc = (lg & 1) ^ ((row >> 1) & 3);
        boff[j] = (uint32_t)(row*64 + swc*16);
    }

    const int NK = E_DIM / BK;   // 16
    load_tile(0, 0); CP_COMMIT();
    load_tile(1, 1); CP_COMMIT();

    for (int kt = 0; kt < NK; kt++) {
        int stg = kt % NSTG;
        if (kt == NK - 1) { CP_WAIT(0); } else { CP_WAIT(1); }
        __syncthreads();
        if (kt + 2 < NK) { load_tile(kt + 2, (kt + 2) % NSTG); CP_COMMIT(); }

        uint32_t tA = sbase + (uint32_t)stg * STAGE_B;
        uint32_t tB = tA + TILE_B;

        #pragma unroll
        for (int ks = 0; ks < 4; ks++) {
            uint32_t ko = (uint32_t)((ks >> 1) * 8192);
            uint32_t ksx = (uint32_t)((ks & 1) * 32);
            uint32_t aq[2][4], bq[8][2];
            #pragma unroll
            for (int mt = 0; mt < 2; mt++)
                LDSM4(aq[mt], tA + ko + (aoff[mt] ^ ksx));
            #pragma unroll
            for (int j = 0; j < 4; j++) {
                uint32_t rb[4];
                LDSM4(rb, tB + ko + (boff[j] ^ ksx));
                bq[2*j][0] = rb[0]; bq[2*j][1] = rb[1];
                bq[2*j+1][0] = rb[2]; bq[2*j+1][1] = rb[3];
            }
            #pragma unroll
            for (int mt = 0; mt < 2; mt++)
                #pragma unroll
                for (int nt = 0; nt < 8; nt++)
                    mma_f16(acc[mt][nt], aq[mt], bq[nt]);
        }
    }
}

// fused k/v GEMM: z=0 -> k, z=1 -> v, both fp16 out
__global__ void __launch_bounds__(256)
gemm_kv(const __half* __restrict__ Xk, const __half* __restrict__ Wkt,
        const __half* __restrict__ Xv, const __half* __restrict__ Wvt,
        __half* __restrict__ K, __half* __restrict__ V) {
    extern __shared__ uint32_t smem[];
    uint32_t sbase = smem_addr(smem);
    int tid = threadIdx.x;
    int z = blockIdx.z;
    int bm = blockIdx.y * BM, bn = blockIdx.x * BN;

    float acc[2][8][4];
    #pragma unroll
    for (int mt = 0; mt < 2; mt++)
        #pragma unroll
        for (int nt = 0; nt < 8; nt++)
            #pragma unroll
            for (int q = 0; q < 4; q++) acc[mt][nt][q] = 0.f;

    gemm_core(z ? Xv : Xk, z ? Wvt : Wkt, bm, bn, sbase, tid, acc);

    __half* O = z ? V : K;
    int warp = tid >> 5, lane = tid & 31;
    int wm = warp & 3, wn = warp >> 2;
    #pragma unroll
    for (int mt = 0; mt < 2; mt++) {
        int r0 = bm + wm*32 + mt*16 + (lane >> 2);
        #pragma unroll
        for (int nt = 0; nt < 8; nt++) {
            int c0 = bn + wn*64 + nt*8 + ((lane & 3) << 1);
            *(__half2*)(&O[(size_t) r0     *E_DIM + c0]) = __floats2half2_rn(acc[mt][nt][0], acc[mt][nt][1]);
            *(__half2*)(&O[(size_t)(r0 + 8)*E_DIM + c0]) = __floats2half2_rn(acc[mt][nt][2], acc[mt][nt][3]);
        }
    }
}

// plain GEMM (fp32 out) for the output projection
__global__ void __launch_bounds__(256)
gemm_f16_1p(const __half* __restrict__ Aq, const __half* __restrict__ Bq,
            float* __restrict__ C) {
    extern __shared__ uint32_t smem[];
    uint32_t sbase = smem_addr(smem);
    int tid = threadIdx.x;
    int bm = blockIdx.y * BM, bn = blockIdx.x * BN;

    float acc[2][8][4];
    #pragma unroll
    for (int mt = 0; mt < 2; mt++)
        #pragma unroll
        for (int nt = 0; nt < 8; nt++)
            #pragma unroll
            for (int q = 0; q < 4; q++) acc[mt][nt][q] = 0.f;

    gemm_core(Aq, Bq, bm, bn, sbase, tid, acc);

    int warp = tid >> 5, lane = tid & 31;
    int wm = warp & 3, wn = warp >> 2;
    #pragma unroll
    for (int mt = 0; mt < 2; mt++) {
        int r0 = bm + wm*32 + mt*16 + (lane >> 2);
        #pragma unroll
        for (int nt = 0; nt < 8; nt++) {
            int c0 = bn + wn*64 + nt*8 + ((lane & 3) << 1);
            *(float2*)(&C[(size_t) r0     *E_DIM + c0]) = make_float2(acc[mt][nt][0], acc[mt][nt][1]);
            *(float2*)(&C[(size_t)(r0 + 8)*E_DIM + c0]) = make_float2(acc[mt][nt][2], acc[mt][nt][3]);
        }
    }
}

// ============================================================
// 3) chunked associative exp-scan (k, v fp16; 8 channels/thread)
// ============================================================
__device__ __forceinline__ void scan_step(float& a, float& b, float& p,
                                          float w, float k, float v) {
    float pw = p + w;
    float d  = pw - k;
    float e  = __expf(-fabsf(d));
    float e1 = (d >= 0.f) ? 1.f : e;
    float e2 = (d >= 0.f) ? e   : 1.f;
    a = a*e1 + v*e2;
    b = b*e1 + e2;
    p = fmaxf(pw, k);
}

__device__ __forceinline__ void seg_combine(float aL, float bL, float pL,
                                            float& a, float& b, float& p,
                                            float cwLw) {
    float pw = pL + cwLw;
    float d  = pw - p;
    float e  = __expf(-fabsf(d));
    float e1 = (d >= 0.f) ? 1.f : e;
    float e2 = (d >= 0.f) ? e   : 1.f;
    a = aL*e1 + a*e2;
    b = bL*e1 + b*e2;
    p = fmaxf(pw, p);
}

__device__ __forceinline__ void load_h8(const __half* base, size_t off, float v[8]) {
    uint4 raw = *(const uint4*)((const unsigned short*)base + off);
    float2 f;
    f = __half22float2(*(__half2*)&raw.x); v[0] = f.x; v[1] = f.y;
    f = __half22float2(*(__half2*)&raw.y); v[2] = f.x; v[3] = f.y;
    f = __half22float2(*(__half2*)&raw.z); v[4] = f.x; v[5] = f.y;
    f = __half22float2(*(__half2*)&raw.w); v[6] = f.x; v[7] = f.y;
}

__global__ void scan_pass1(const float* __restrict__ time_decay) {
    int tid = blockIdx.x * blockDim.x + threadIdx.x;   // NCHUNK*CH8 threads
    int c = tid >> 10, ch8 = tid & (CH8 - 1);
    int ch = ch8 * 8;
    int e  = ch & (E_DIM - 1);
    float wv[8], a[8], b[8], p[8];
    *(float4*)&wv[0] = *(const float4*)(time_decay + e);
    *(float4*)&wv[4] = *(const float4*)(time_decay + e + 4);
    #pragma unroll
    for (int j = 0; j < 8; j++) { a[j] = 0.f; b[j] = 0.f; p[j] = -1e30f; }
    int base = c * CLEN;
    for (int t0 = 0; t0 < CLEN; t0 += 2) {
        float kk[2][8], vv[2][8];
        #pragma unroll
        for (int i = 0; i < 2; i++) {
            size_t off = (size_t)(base + t0 + i) * CH + ch;
            load_h8(g_kh, off, kk[i]);
            load_h8(g_vh, off, vv[i]);
        }
        #pragma unroll
        for (int i = 0; i < 2; i++)
            #pragma unroll
            for (int j = 0; j < 8; j++)
                scan_step(a[j], b[j], p[j], wv[j], kk[i][j], vv[i][j]);
    }
    *(float4*)(g_agg +                     (size_t)c*CH + ch)     = *(float4*)&a[0];
    *(float4*)(g_agg +                     (size_t)c*CH + ch + 4) = *(float4*)&a[4];
    *(float4*)(g_agg + (size_t)NCHUNK*CH + (size_t)c*CH + ch)     = *(float4*)&b[0];
    *(float4*)(g_agg + (size_t)NCHUNK*CH + (size_t)c*CH + ch + 4) = *(float4*)&b[4];
    *(float4*)(g_agg + 2*(size_t)NCHUNK*CH + (size_t)c*CH + ch)     = *(float4*)&p[0];
    *(float4*)(g_agg + 2*(size_t)NCHUNK*CH + (size_t)c*CH + ch + 4) = *(float4*)&p[4];
}

// warp-parallel exclusive scan over NCHUNK=256 chunks, conflict-free smem.
// block = 256 threads = 8 warps = 8 channels; 8 chunks per lane.
__global__ void scan_pass2(const float* __restrict__ time_decay) {
    __shared__ float s[3][8][264];
    int ch0 = blockIdx.x * 8;
    int tid = threadIdx.x;

    #pragma unroll
    for (int i = 0; i < NCHUNK*8/256; i++) {
        int idx = tid + i*256;
        int c = idx >> 3, j = idx & 7;
        s[0][j][c] = g_agg[                     (size_t)c*CH + ch0 + j];
        s[1][j][c] = g_agg[(size_t)NCHUNK*CH + (size_t)c*CH + ch0 + j];
        s[2][j][c] = g_agg[2*(size_t)NCHUNK*CH + (size_t)c*CH + ch0 + j];
    }
    __syncthreads();

    int w = tid >> 5, lane = tid & 31;
    float wdec = time_decay[(ch0 + w) & (E_DIM - 1)];
    float Lw = (float)CLEN * wdec;
    int cbase = lane * 8;

    float la[8], lb[8], lp[8];
    #pragma unroll
    for (int i = 0; i < 8; i += 4) {
        *(float4*)&la[i] = *(float4*)&s[0][w][cbase + i];
        *(float4*)&lb[i] = *(float4*)&s[1][w][cbase + i];
        *(float4*)&lp[i] = *(float4*)&s[2][w][cbase + i];
    }

    float A = la[0], B = lb[0], P = lp[0];
    #pragma unroll
    for (int i = 1; i < 8; i++) {
        float a2 = la[i], b2 = lb[i], p2 = lp[i];
        seg_combine(A, B, P, a2, b2, p2, Lw);
        A = a2; B = b2; P = p2;
    }
    int cnt = 8;
    #pragma unroll
    for (int d = 1; d < 32; d <<= 1) {
        float aL = __shfl_up_sync(0xffffffffu, A, d);
        float bL = __shfl_up_sync(0xffffffffu, B, d);
        float pL = __shfl_up_sync(0xffffffffu, P, d);
        int   cL = __shfl_up_sync(0xffffffffu, cnt, d);
        if (lane >= d) {
            seg_combine(aL, bL, pL, A, B, P, (float)cnt * Lw);
            cnt += cL;
        }
    }
    float ae = __shfl_up_sync(0xffffffffu, A, 1);
    float be = __shfl_up_sync(0xffffffffu, B, 1);
    float pe = __shfl_up_sync(0xffffffffu, P, 1);
    if (lane == 0) { ae = 0.f; be = 0.f; pe = -1e30f; }

    float oa[8], ob[8], op[8];
    #pragma unroll
    for (int i = 0; i < 8; i++) {
        oa[i] = ae; ob[i] = be; op[i] = pe;
        if (i < 7) {
            float a2 = la[i], b2 = lb[i], p2 = lp[i];
            seg_combine(ae, be, pe, a2, b2, p2, Lw);
            ae = a2; be = b2; pe = p2;
        }
    }
    #pragma unroll
    for (int i = 0; i < 8; i += 4) {
        *(float4*)&s[0][w][cbase + i] = *(float4*)&oa[i];
        *(float4*)&s[1][w][cbase + i] = *(float4*)&ob[i];
        *(float4*)&s[2][w][cbase + i] = *(float4*)&op[i];
    }
    __syncthreads();

    #pragma unroll
    for (int i = 0; i < NCHUNK*8/256; i++) {
        int idx = tid + i*256;
        int c = idx >> 3, j = idx & 7;
        g_pre[                     (size_t)c*CH + ch0 + j] = s[0][j][c];
        g_pre[(size_t)NCHUNK*CH + (size_t)c*CH + ch0 + j] = s[1][j][c];
        g_pre[2*(size_t)NCHUNK*CH + (size_t)c*CH + ch0 + j] = s[2][j][c];
    }
}

__global__ void scan_pass3(const float* __restrict__ time_decay,
                           const float* __restrict__ time_first) {
    int tid = blockIdx.x * blockDim.x + threadIdx.x;
    int c = tid >> 10, ch8 = tid & (CH8 - 1);
    int ch = ch8 * 8;
    int e  = ch & (E_DIM - 1);
    float wv[8], uv[8], a[8], b[8], p[8];
    *(float4*)&wv[0] = *(const float4*)(time_decay + e);
    *(float4*)&wv[4] = *(const float4*)(time_decay + e + 4);
    *(float4*)&uv[0] = *(const float4*)(time_first + e);
    *(float4*)&uv[4] = *(const float4*)(time_first + e + 4);
    *(float4*)&a[0] = *(const float4*)(g_pre +                     (size_t)c*CH + ch);
    *(float4*)&a[4] = *(const float4*)(g_pre +                     (size_t)c*CH + ch + 4);
    *(float4*)&b[0] = *(const float4*)(g_pre + (size_t)NCHUNK*CH + (size_t)c*CH + ch);
    *(float4*)&b[4] = *(const float4*)(g_pre + (size_t)NCHUNK*CH + (size_t)c*CH + ch + 4);
    *(float4*)&p[0] = *(const float4*)(g_pre + 2*(size_t)NCHUNK*CH + (size_t)c*CH + ch);
    *(float4*)&p[4] = *(const float4*)(g_pre + 2*(size_t)NCHUNK*CH + (size_t)c*CH + ch + 4);
    int base = c * CLEN;
    for (int t0 = 0; t0 < CLEN; t0 += 2) {
        float kk[2][8], vv[2][8];
        #pragma unroll
        for (int i = 0; i < 2; i++) {
            size_t off = (size_t)(base + t0 + i) * CH + ch;
            load_h8(g_kh, off, kk[i]);
            load_h8(g_vh, off, vv[i]);
        }
        #pragma unroll
        for (int i = 0; i < 2; i++) {
            unsigned short qs[8];
            #pragma unroll
            for (int j = 0; j < 8; j++) {
                scan_step(a[j], b[j], p[j], wv[j], kk[i][j], vv[i][j]);
                float kb = kk[i][j] + uv[j] + wv[j];
                float d2 = p[j] - kb;
                float eo = __expf(-fabsf(d2));
                float o1 = (d2 >= 0.f) ? 1.f : eo;
                float o2 = (d2 >= 0.f) ? eo  : 1.f;
                float cn = a[j]*o1 + vv[i][j]*o2;
                float dn = b[j]*o1 + o2;
                qs[j] = __half_as_ushort(__float2half_rn(__fdividef(cn, dn)));
            }
            size_t off = (size_t)(base + t0 + i) * CH + ch;
            uint4 outq;
            outq.x = (uint32_t)qs[0] | ((uint32_t)qs[1] << 16);
            outq.y = (uint32_t)qs[2] | ((uint32_t)qs[3] << 16);
            outq.z = (uint32_t)qs[4] | ((uint32_t)qs[5] << 16);
            outq.w = (uint32_t)qs[6] | ((uint32_t)qs[7] << 16);
            *(uint4*)((unsigned short*)g_r + off) = outq;
        }
    }
}

// ============================================================
// launch
// ============================================================
extern "C" void kernel_launch(void* const* d_in, const int* in_sizes, int n_in,
                              void* d_out, int out_size) {
    const float* x     = (const float*)d_in[0];
    const float* tmrkv = (const float*)d_in[1];
    const float* Wk    = (const float*)d_in[2];
    const float* Wv    = (const float*)d_in[3];
    const float* td    = (const float*)d_in[4];
    const float* tf    = (const float*)d_in[5];
    const float* Wout  = (const float*)d_in[6];
    float* out = (float*)d_out;

    cudaFuncSetAttribute(gemm_kv,
                         cudaFuncAttributeMaxDynamicSharedMemorySize, GEMM_SMEM);
    cudaFuncSetAttribute(gemm_f16_1p,
                         cudaFuncAttributeMaxDynamicSharedMemorySize, GEMM_SMEM);

    __half *p_xk, *p_xv, *p_r, *p_wk, *p_wv, *p_wo, *p_kh, *p_vh;
    cudaGetSymbolAddress((void**)&p_xk, g_xk);
    cudaGetSymbolAddress((void**)&p_xv, g_xv);
    cudaGetSymbolAddress((void**)&p_r,  g_r);
    cudaGetSymbolAddress((void**)&p_wk, g_wkt);
    cudaGetSymbolAddress((void**)&p_wv, g_wvt);
    cudaGetSymbolAddress((void**)&p_wo, g_wot);
    cudaGetSymbolAddress((void**)&p_kh, g_kh);
    cudaGetSymbolAddress((void**)&p_vh, g_vh);

    // 1) fused prep: mix + 3x weight transpose
    prep_kernel<<<MIXB + 3*1024, 256>>>(x, tmrkv, Wk, Wv, Wout);

    // 2) fused k/v GEMM
    dim3 kvgrid(E_DIM/BN, M_TOT/BM, 2);   // (8, 128, 2)
    gemm_kv<<<kvgrid, 256, GEMM_SMEM>>>(p_xk, p_wk, p_xv, p_wv, p_kh, p_vh);

    // 3) scan
    scan_pass1<<<(NCHUNK*CH8)/256, 256>>>(td);
    scan_pass2<<<CH/8, 256>>>(td);
    scan_pass3<<<(NCHUNK*CH8)/256, 256>>>(td, tf);

    // 4) out = rwkv @ Wout
    dim3 ggrid(E_DIM/BN, M_TOT/BM);
    gemm_f16_1p<<<ggrid, 256, GEMM_SMEM>>>(p_r, p_wo, out);
}

// round 17
// speedup vs baseline: 1.0126x; 1.0126x over previous
#include <cuda_runtime.h>
#include <cuda_fp16.h>
#include <cstdint>
#include <cstddef>

#define S_LEN 2048
#define B_DIM 8
#define E_DIM 1024
#define M_TOT (S_LEN*B_DIM)      // 16384
#define CH    (B_DIM*E_DIM)      // 8192
#define NCHUNK 128
#define CLEN  (S_LEN/NCHUNK)     // 16
#define CH8   (CH/8)             // 1024

// ---------------- scratch (device globals; no allocation allowed) ------------
__device__ __half g_xk[(size_t)M_TOT*E_DIM];
__device__ __half g_xv[(size_t)M_TOT*E_DIM];
__device__ __half g_r [(size_t)M_TOT*E_DIM];
__device__ __half g_kh[(size_t)M_TOT*E_DIM];
__device__ __half g_vh[(size_t)M_TOT*E_DIM];
__device__ __half g_wkt[(size_t)E_DIM*E_DIM];
__device__ __half g_wvt[(size_t)E_DIM*E_DIM];
__device__ __half g_wot[(size_t)E_DIM*E_DIM];
__device__ float g_agg[3*NCHUNK*CH];
__device__ float g_pre[3*NCHUNK*CH];

// ---------------- helpers ----------------------------------------------------
__device__ __forceinline__ uint32_t smem_addr(const void* p) {
    uint32_t a;
    asm("{ .reg .u64 t; cvta.to.shared.u64 t, %1; cvt.u32.u64 %0, t; }" : "=r"(a) : "l"(p));
    return a;
}
#define CP_ASYNC16(dst, src) \
    asm volatile("cp.async.cg.shared.global [%0], [%1], 16;" :: "r"(dst), "l"(src) : "memory")
#define CP_COMMIT() asm volatile("cp.async.commit_group;" ::: "memory")
#define CP_WAIT(n)  asm volatile("cp.async.wait_group %0;" :: "n"(n) : "memory")

#define LDSM4(r, addr) \
    asm volatile("ldmatrix.sync.aligned.m8n8.x4.shared.b16 {%0,%1,%2,%3}, [%4];" \
        : "=r"((r)[0]), "=r"((r)[1]), "=r"((r)[2]), "=r"((r)[3]) : "r"(addr))

__device__ __forceinline__ void mma_f16(float c[4], const uint32_t a[4], const uint32_t b[2]) {
    asm volatile(
        "mma.sync.aligned.m16n8k16.row.col.f32.f16.f16.f32 "
        "{%0,%1,%2,%3}, {%4,%5,%6,%7}, {%8,%9}, {%0,%1,%2,%3};\n"
        : "+f"(c[0]), "+f"(c[1]), "+f"(c[2]), "+f"(c[3])
        : "r"(a[0]), "r"(a[1]), "r"(a[2]), "r"(a[3]), "r"(b[0]), "r"(b[1]));
}

// ============================================================
// 1) fused prep: token mix + fp16 quantize  AND  3x weight transpose
// ============================================================
#define MIXB (M_TOT*E_DIM/4/256)   // 16384

__global__ void prep_kernel(const float* __restrict__ x,
                            const float* __restrict__ tmrkv,
                            const float* __restrict__ Wk,
                            const float* __restrict__ Wv,
                            const float* __restrict__ Wout) {
    __shared__ float t[32][33];
    int blk = blockIdx.x;
    int tid = threadIdx.x;

    if (blk < MIXB) {
        int i4  = blk * 256 + tid;
        int idx = i4 * 4;
        int e   = idx & (E_DIM - 1);
        float4 xc = *(const float4*)(x + idx);
        float4 xp = make_float4(0.f, 0.f, 0.f, 0.f);
        if (idx >= CH) xp = *(const float4*)(x + idx - CH);
        float4 mk = *(const float4*)(tmrkv + E_DIM   + e);
        float4 mv = *(const float4*)(tmrkv + 2*E_DIM + e);
        float ok[4], ov[4];
        ok[0] = mk.x*xc.x + (1.f-mk.x)*xp.x;  ov[0] = mv.x*xc.x + (1.f-mv.x)*xp.x;
        ok[1] = mk.y*xc.y + (1.f-mk.y)*xp.y;  ov[1] = mv.y*xc.y + (1.f-mv.y)*xp.y;
        ok[2] = mk.z*xc.z + (1.f-mk.z)*xp.z;  ov[2] = mv.z*xc.z + (1.f-mv.z)*xp.z;
        ok[3] = mk.w*xc.w + (1.f-mk.w)*xp.w;  ov[3] = mv.w*xc.w + (1.f-mv.w)*xp.w;
        ushort4 kq, vq;
        kq.x = __half_as_ushort(__float2half_rn(ok[0]));
        kq.y = __half_as_ushort(__float2half_rn(ok[1]));
        kq.z = __half_as_ushort(__float2half_rn(ok[2]));
        kq.w = __half_as_ushort(__float2half_rn(ok[3]));
        vq.x = __half_as_ushort(__float2half_rn(ov[0]));
        vq.y = __half_as_ushort(__float2half_rn(ov[1]));
        vq.z = __half_as_ushort(__float2half_rn(ov[2]));
        vq.w = __half_as_ushort(__float2half_rn(ov[3]));
        *(ushort4*)((unsigned short*)g_xk + idx) = kq;
        *(ushort4*)((unsigned short*)g_xv + idx) = vq;
    } else {
        int wb   = blk - MIXB;
        int widx = wb >> 10;          // 0,1,2
        int tb   = wb & 1023;
        const float* W = (widx == 0) ? Wk : (widx == 1) ? Wv : Wout;
        __half* T = (widx == 0) ? g_wkt : (widx == 1) ? g_wvt : g_wot;
        int bx = (tb & 31) * 32;      // n block
        int by = (tb >> 5) * 32;      // k block
        int tx = tid & 31, ty = tid >> 5;   // 32 x 8
        for (int j = ty; j < 32; j += 8)
            t[j][tx] = W[(size_t)(by + j) * E_DIM + bx + tx];
        __syncthreads();
        for (int j = ty; j < 32; j += 8) {
            float v = t[tx][j];
            T[(size_t)(bx + j) * E_DIM + by + tx] = __float2half_rn(v);
        }
    }
}

// ============================================================
// 2) 1-product fp16 GEMM core (128x128 tile, BK=64, 256 thr, NSTG=3)
// ============================================================
#define BM 128
#define BN 128
#define BK 64
#define TILE_B 16384               // 128 rows * 128 bytes
#define STAGE_B (2*TILE_B)         // 32768
#define NSTG 3
#define GEMM_SMEM (NSTG*STAGE_B)   // 98304 -> 2 CTAs/SM

__device__ __forceinline__ void gemm_core(const __half* __restrict__ Aq,
                                          const __half* __restrict__ Bq,
                                          int bm, int bn,
                                          uint32_t sbase, int tid,
                                          float acc[2][8][4]) {
    int warp = tid >> 5, lane = tid & 31;
    int wm = warp & 3, wn = warp >> 2;

    const char* srcs[2] = {
        (const char*)(Aq + (size_t)bm * E_DIM),
        (const char*)(Bq + (size_t)bn * E_DIM) };

    auto load_tile = [&](int kt, int stg) {
        uint32_t dst0 = sbase + (uint32_t)stg * STAGE_B;
        int koff = kt * (BK*2);    // 128 bytes per k-tile
        #pragma unroll
        for (int arr = 0; arr < 2; arr++) {
            #pragma unroll
            for (int i = 0; i < 4; i++) {
                int f = tid + i*256;
                int row = f >> 3, chunk = f & 7;
                int ksl = chunk >> 2, ch = chunk & 3;
                int sw = ch ^ ((row >> 1) & 3);
                uint32_t dst = dst0 + arr*TILE_B + ksl*8192 + row*64 + sw*16;
                const char* src = srcs[arr] + (size_t)row * (E_DIM*2) + koff + chunk*16;
                CP_ASYNC16(dst, src);
            }
        }
    };

    int lm = lane & 7, lg = lane >> 3;
    uint32_t aoff[2];
    #pragma unroll
    for (int mt = 0; mt < 2; mt++) {
        int row = wm*32 + mt*16 + (lg & 1)*8 + lm;
        int swc = (lg >> 1) ^ ((row >> 1) & 3);
        aoff[mt] = (uint32_t)(row*64 + swc*16);
    }
    uint32_t boff[4];
    #pragma unroll
    for (int j = 0; j < 4; j++) {
        int row = wn*64 + j*16 + (lg >> 1)*8 + lm;
        int swc = (lg & 1) ^ ((row >> 1) & 3);
        boff[j] = (uint32_t)(row*64 + swc*16);
    }

    const int NK = E_DIM / BK;   // 16
    load_tile(0, 0); CP_COMMIT();
    load_tile(1, 1); CP_COMMIT();

    for (int kt = 0; kt < NK; kt++) {
        int stg = kt % NSTG;
        if (kt == NK - 1) { CP_WAIT(0); } else { CP_WAIT(1); }
        __syncthreads();
        if (kt + 2 < NK) { load_tile(kt + 2, (kt + 2) % NSTG); CP_COMMIT(); }

        uint32_t tA = sbase + (uint32_t)stg * STAGE_B;
        uint32_t tB = tA + TILE_B;

        #pragma unroll
        for (int ks = 0; ks < 4; ks++) {
            uint32_t ko = (uint32_t)((ks >> 1) * 8192);
            uint32_t ksx = (uint32_t)((ks & 1) * 32);
            uint32_t aq[2][4], bq[8][2];
            #pragma unroll
            for (int mt = 0; mt < 2; mt++)
                LDSM4(aq[mt], tA + ko + (aoff[mt] ^ ksx));
            #pragma unroll
            for (int j = 0; j < 4; j++) {
                uint32_t rb[4];
                LDSM4(rb, tB + ko + (boff[j] ^ ksx));
                bq[2*j][0] = rb[0]; bq[2*j][1] = rb[1];
                bq[2*j+1][0] = rb[2]; bq[2*j+1][1] = rb[3];
            }
            #pragma unroll
            for (int mt = 0; mt < 2; mt++)
                #pragma unroll
                for (int nt = 0; nt < 8; nt++)
                    mma_f16(acc[mt][nt], aq[mt], bq[nt]);
        }
    }
}

// fused k/v GEMM: z=0 -> k, z=1 -> v, both fp16 out
__global__ void __launch_bounds__(256)
gemm_kv(const __half* __restrict__ Xk, const __half* __restrict__ Wkt,
        const __half* __restrict__ Xv, const __half* __restrict__ Wvt,
        __half* __restrict__ K, __half* __restrict__ V) {
    extern __shared__ uint32_t smem[];
    uint32_t sbase = smem_addr(smem);
    int tid = threadIdx.x;
    int z = blockIdx.z;
    int bm = blockIdx.y * BM, bn = blockIdx.x * BN;

    float acc[2][8][4];
    #pragma unroll
    for (int mt = 0; mt < 2; mt++)
        #pragma unroll
        for (int nt = 0; nt < 8; nt++)
            #pragma unroll
            for (int q = 0; q < 4; q++) acc[mt][nt][q] = 0.f;

    gemm_core(z ? Xv : Xk, z ? Wvt : Wkt, bm, bn, sbase, tid, acc);

    __half* O = z ? V : K;
    int warp = tid >> 5, lane = tid & 31;
    int wm = warp & 3, wn = warp >> 2;
    #pragma unroll
    for (int mt = 0; mt < 2; mt++) {
        int r0 = bm + wm*32 + mt*16 + (lane >> 2);
        #pragma unroll
        for (int nt = 0; nt < 8; nt++) {
            int c0 = bn + wn*64 + nt*8 + ((lane & 3) << 1);
            *(__half2*)(&O[(size_t) r0     *E_DIM + c0]) = __floats2half2_rn(acc[mt][nt][0], acc[mt][nt][1]);
            *(__half2*)(&O[(size_t)(r0 + 8)*E_DIM + c0]) = __floats2half2_rn(acc[mt][nt][2], acc[mt][nt][3]);
        }
    }
}

// plain GEMM (fp32 out) for the output projection
__global__ void __launch_bounds__(256)
gemm_f16_1p(const __half* __restrict__ Aq, const __half* __restrict__ Bq,
            float* __restrict__ C) {
    extern __shared__ uint32_t smem[];
    uint32_t sbase = smem_addr(smem);
    int tid = threadIdx.x;
    int bm = blockIdx.y * BM, bn = blockIdx.x * BN;

    float acc[2][8][4];
    #pragma unroll
    for (int mt = 0; mt < 2; mt++)
        #pragma unroll
        for (int nt = 0; nt < 8; nt++)
            #pragma unroll
            for (int q = 0; q < 4; q++) acc[mt][nt][q] = 0.f;

    gemm_core(Aq, Bq, bm, bn, sbase, tid, acc);

    int warp = tid >> 5, lane = tid & 31;
    int wm = warp & 3, wn = warp >> 2;
    #pragma unroll
    for (int mt = 0; mt < 2; mt++) {
        int r0 = bm + wm*32 + mt*16 + (lane >> 2);
        #pragma unroll
        for (int nt = 0; nt < 8; nt++) {
            int c0 = bn + wn*64 + nt*8 + ((lane & 3) << 1);
            *(float2*)(&C[(size_t) r0     *E_DIM + c0]) = make_float2(acc[mt][nt][0], acc[mt][nt][1]);
            *(float2*)(&C[(size_t)(r0 + 8)*E_DIM + c0]) = make_float2(acc[mt][nt][2], acc[mt][nt][3]);
        }
    }
}

// ============================================================
// 3) chunked associative exp-scan (k, v fp16; 8 channels/thread)
// ============================================================
__device__ __forceinline__ void scan_step(float& a, float& b, float& p,
                                          float w, float k, float v) {
    float pw = p + w;
    float d  = pw - k;
    float e  = __expf(-fabsf(d));
    float e1 = (d >= 0.f) ? 1.f : e;
    float e2 = (d >= 0.f) ? e   : 1.f;
    a = a*e1 + v*e2;
    b = b*e1 + e2;
    p = fmaxf(pw, k);
}

__device__ __forceinline__ void seg_combine(float aL, float bL, float pL,
                                            float& a, float& b, float& p,
                                            float cwLw) {
    float pw = pL + cwLw;
    float d  = pw - p;
    float e  = __expf(-fabsf(d));
    float e1 = (d >= 0.f) ? 1.f : e;
    float e2 = (d >= 0.f) ? e   : 1.f;
    a = aL*e1 + a*e2;
    b = bL*e1 + b*e2;
    p = fmaxf(pw, p);
}

__device__ __forceinline__ void load_h8(const __half* base, size_t off, float v[8]) {
    uint4 raw = *(const uint4*)((const unsigned short*)base + off);
    float2 f;
    f = __half22float2(*(__half2*)&raw.x); v[0] = f.x; v[1] = f.y;
    f = __half22float2(*(__half2*)&raw.y); v[2] = f.x; v[3] = f.y;
    f = __half22float2(*(__half2*)&raw.z); v[4] = f.x; v[5] = f.y;
    f = __half22float2(*(__half2*)&raw.w); v[6] = f.x; v[7] = f.y;
}

__global__ void scan_pass1(const float* __restrict__ time_decay) {
    int tid = blockIdx.x * blockDim.x + threadIdx.x;   // NCHUNK*CH8 threads
    int c = tid >> 10, ch8 = tid & (CH8 - 1);
    int ch = ch8 * 8;
    int e  = ch & (E_DIM - 1);
    float wv[8], a[8], b[8], p[8];
    *(float4*)&wv[0] = *(const float4*)(time_decay + e);
    *(float4*)&wv[4] = *(const float4*)(time_decay + e + 4);
    #pragma unroll
    for (int j = 0; j < 8; j++) { a[j] = 0.f; b[j] = 0.f; p[j] = -1e30f; }
    int base = c * CLEN;
    for (int t0 = 0; t0 < CLEN; t0 += 2) {
        float kk[2][8], vv[2][8];
        #pragma unroll
        for (int i = 0; i < 2; i++) {
            size_t off = (size_t)(base + t0 + i) * CH + ch;
            load_h8(g_kh, off, kk[i]);
            load_h8(g_vh, off, vv[i]);
        }
        #pragma unroll
        for (int i = 0; i < 2; i++)
            #pragma unroll
            for (int j = 0; j < 8; j++)
                scan_step(a[j], b[j], p[j], wv[j], kk[i][j], vv[i][j]);
    }
    *(float4*)(g_agg +               c*CH + ch)     = *(float4*)&a[0];
    *(float4*)(g_agg +               c*CH + ch + 4) = *(float4*)&a[4];
    *(float4*)(g_agg +   NCHUNK*CH + c*CH + ch)     = *(float4*)&b[0];
    *(float4*)(g_agg +   NCHUNK*CH + c*CH + ch + 4) = *(float4*)&b[4];
    *(float4*)(g_agg + 2*NCHUNK*CH + c*CH + ch)     = *(float4*)&p[0];
    *(float4*)(g_agg + 2*NCHUNK*CH + c*CH + ch + 4) = *(float4*)&p[4];
}

// warp-parallel exclusive scan over NCHUNK=128 chunks, conflict-free smem.
// block = 256 threads = 8 warps = 8 channels; 4 chunks per lane. (round-15 proven)
__global__ void scan_pass2(const float* __restrict__ time_decay) {
    __shared__ float s[3][8][132];
    int ch0 = blockIdx.x * 8;
    int tid = threadIdx.x;

    #pragma unroll
    for (int i = 0; i < NCHUNK*8/256; i++) {
        int idx = tid + i*256;
        int c = idx >> 3, j = idx & 7;
        s[0][j][c] = g_agg[              c*CH + ch0 + j];
        s[1][j][c] = g_agg[  NCHUNK*CH + c*CH + ch0 + j];
        s[2][j][c] = g_agg[2*NCHUNK*CH + c*CH + ch0 + j];
    }
    __syncthreads();

    int w = tid >> 5, lane = tid & 31;
    float wdec = time_decay[(ch0 + w) & (E_DIM - 1)];
    float Lw = (float)CLEN * wdec;
    int cbase = lane * 4;

    float4 a4 = *(float4*)&s[0][w][cbase];
    float4 b4 = *(float4*)&s[1][w][cbase];
    float4 p4 = *(float4*)&s[2][w][cbase];
    float la[4] = {a4.x,a4.y,a4.z,a4.w};
    float lb[4] = {b4.x,b4.y,b4.z,b4.w};
    float lp[4] = {p4.x,p4.y,p4.z,p4.w};

    float A = la[0], B = lb[0], P = lp[0];
    #pragma unroll
    for (int i = 1; i < 4; i++) {
        float a2 = la[i], b2 = lb[i], p2 = lp[i];
        seg_combine(A, B, P, a2, b2, p2, Lw);
        A = a2; B = b2; P = p2;
    }
    int cnt = 4;
    #pragma unroll
    for (int d = 1; d < 32; d <<= 1) {
        float aL = __shfl_up_sync(0xffffffffu, A, d);
        float bL = __shfl_up_sync(0xffffffffu, B, d);
        float pL = __shfl_up_sync(0xffffffffu, P, d);
        int   cL = __shfl_up_sync(0xffffffffu, cnt, d);
        if (lane >= d) {
            seg_combine(aL, bL, pL, A, B, P, (float)cnt * Lw);
            cnt += cL;
        }
    }
    float ae = __shfl_up_sync(0xffffffffu, A, 1);
    float be = __shfl_up_sync(0xffffffffu, B, 1);
    float pe = __shfl_up_sync(0xffffffffu, P, 1);
    if (lane == 0) { ae = 0.f; be = 0.f; pe = -1e30f; }

    float oa[4], ob[4], op[4];
    #pragma unroll
    for (int i = 0; i < 4; i++) {
        oa[i] = ae; ob[i] = be; op[i] = pe;
        if (i < 3) {
            float a2 = la[i], b2 = lb[i], p2 = lp[i];
            seg_combine(ae, be, pe, a2, b2, p2, Lw);
            ae = a2; be = b2; pe = p2;
        }
    }
    *(float4*)&s[0][w][cbase] = make_float4(oa[0],oa[1],oa[2],oa[3]);
    *(float4*)&s[1][w][cbase] = make_float4(ob[0],ob[1],ob[2],ob[3]);
    *(float4*)&s[2][w][cbase] = make_float4(op[0],op[1],op[2],op[3]);
    __syncthreads();

    #pragma unroll
    for (int i = 0; i < NCHUNK*8/256; i++) {
        int idx = tid + i*256;
        int c = idx >> 3, j = idx & 7;
        g_pre[              c*CH + ch0 + j] = s[0][j][c];
        g_pre[  NCHUNK*CH + c*CH + ch0 + j] = s[1][j][c];
        g_pre[2*NCHUNK*CH + c*CH + ch0 + j] = s[2][j][c];
    }
}

__global__ void scan_pass3(const float* __restrict__ time_decay,
                           const float* __restrict__ time_first) {
    int tid = blockIdx.x * blockDim.x + threadIdx.x;
    int c = tid >> 10, ch8 = tid & (CH8 - 1);
    int ch = ch8 * 8;
    int e  = ch & (E_DIM - 1);
    float wv[8], uv[8], a[8], b[8], p[8];
    *(float4*)&wv[0] = *(const float4*)(time_decay + e);
    *(float4*)&wv[4] = *(const float4*)(time_decay + e + 4);
    *(float4*)&uv[0] = *(const float4*)(time_first + e);
    *(float4*)&uv[4] = *(const float4*)(time_first + e + 4);
    *(float4*)&a[0] = *(const float4*)(g_pre +               c*CH + ch);
    *(float4*)&a[4] = *(const float4*)(g_pre +               c*CH + ch + 4);
    *(float4*)&b[0] = *(const float4*)(g_pre +   NCHUNK*CH + c*CH + ch);
    *(float4*)&b[4] = *(const float4*)(g_pre +   NCHUNK*CH + c*CH + ch + 4);
    *(float4*)&p[0] = *(const float4*)(g_pre + 2*NCHUNK*CH + c*CH + ch);
    *(float4*)&p[4] = *(const float4*)(g_pre + 2*NCHUNK*CH + c*CH + ch + 4);
    int base = c * CLEN;
    for (int t0 = 0; t0 < CLEN; t0 += 2) {
        float kk[2][8], vv[2][8];
        #pragma unroll
        for (int i = 0; i < 2; i++) {
            size_t off = (size_t)(base + t0 + i) * CH + ch;
            load_h8(g_kh, off, kk[i]);
            load_h8(g_vh, off, vv[i]);
        }
        #pragma unroll
        for (int i = 0; i < 2; i++) {
            unsigned short qs[8];
            #pragma unroll
            for (int j = 0; j < 8; j++) {
                scan_step(a[j], b[j], p[j], wv[j], kk[i][j], vv[i][j]);
                float kb = kk[i][j] + uv[j] + wv[j];
                float d2 = p[j] - kb;
                float eo = __expf(-fabsf(d2));
                float o1 = (d2 >= 0.f) ? 1.f : eo;
                float o2 = (d2 >= 0.f) ? eo  : 1.f;
                float cn = a[j]*o1 + vv[i][j]*o2;
                float dn = b[j]*o1 + o2;
                qs[j] = __half_as_ushort(__float2half_rn(__fdividef(cn, dn)));
            }
            size_t off = (size_t)(base + t0 + i) * CH + ch;
            uint4 outq;
            outq.x = (uint32_t)qs[0] | ((uint32_t)qs[1] << 16);
            outq.y = (uint32_t)qs[2] | ((uint32_t)qs[3] << 16);
            outq.z = (uint32_t)qs[4] | ((uint32_t)qs[5] << 16);
            outq.w = (uint32_t)qs[6] | ((uint32_t)qs[7] << 16);
            *(uint4*)((unsigned short*)g_r + off) = outq;
        }
    }
}

// ============================================================
// launch
// ============================================================
extern "C" void kernel_launch(void* const* d_in, const int* in_sizes, int n_in,
                              void* d_out, int out_size) {
    const float* x     = (const float*)d_in[0];
    const float* tmrkv = (const float*)d_in[1];
    const float* Wk    = (const float*)d_in[2];
    const float* Wv    = (const float*)d_in[3];
    const float* td    = (const float*)d_in[4];
    const float* tf    = (const float*)d_in[5];
    const float* Wout  = (const float*)d_in[6];
    float* out = (float*)d_out;

    cudaFuncSetAttribute(gemm_kv,
                         cudaFuncAttributeMaxDynamicSharedMemorySize, GEMM_SMEM);
    cudaFuncSetAttribute(gemm_f16_1p,
                         cudaFuncAttributeMaxDynamicSharedMemorySize, GEMM_SMEM);

    __half *p_xk, *p_xv, *p_r, *p_wk, *p_wv, *p_wo, *p_kh, *p_vh;
    cudaGetSymbolAddress((void**)&p_xk, g_xk);
    cudaGetSymbolAddress((void**)&p_xv, g_xv);
    cudaGetSymbolAddress((void**)&p_r,  g_r);
    cudaGetSymbolAddress((void**)&p_wk, g_wkt);
    cudaGetSymbolAddress((void**)&p_wv, g_wvt);
    cudaGetSymbolAddress((void**)&p_wo, g_wot);
    cudaGetSymbolAddress((void**)&p_kh, g_kh);
    cudaGetSymbolAddress((void**)&p_vh, g_vh);

    // 1) fused prep: mix + 3x weight transpose
    prep_kernel<<<MIXB + 3*1024, 256>>>(x, tmrkv, Wk, Wv, Wout);

    // 2) fused k/v GEMM
    dim3 kvgrid(E_DIM/BN, M_TOT/BM, 2);   // (8, 128, 2)
    gemm_kv<<<kvgrid, 256, GEMM_SMEM>>>(p_xk, p_wk, p_xv, p_wv, p_kh, p_vh);

    // 3) scan
    scan_pass1<<<(NCHUNK*CH8)/256, 256>>>(td);
    scan_pass2<<<CH/8, 256>>>(td);
    scan_pass3<<<(NCHUNK*CH8)/256, 256>>>(td, tf);

    // 4) out = rwkv @ Wout
    dim3 ggrid(E_DIM/BN, M_TOT/BM);
    gemm_f16_1p<<<ggrid, 256, GEMM_SMEM>>>(p_r, p_wo, out);
}